// round 11
// baseline (speedup 1.0000x reference)
#include <cuda_runtime.h>
#include <cstdint>

#define MAX_NODES 100000
#define MAX_EDGES 1600000
#define F1 32
#define F2 16
#define F3 2

#define SCAN_B 1024
#define N_SCAN_BLOCKS ((MAX_NODES + SCAN_B - 1) / SCAN_B)   // 98

// Scratch (device globals; no allocation allowed)
__device__ __align__(256) float g_y1[MAX_NODES * F1];
__device__ __align__(256) float g_h1[MAX_NODES * F1];
__device__ __align__(256) float g_y2[MAX_NODES * F2];
__device__ __align__(256) float g_h2[MAX_NODES * F2];
__device__ __align__(256) float g_y3[MAX_NODES * F3];
__device__ __align__(256) float g_h3[MAX_NODES * F3];

__device__ __align__(256) int g_cnt[MAX_NODES];      // in-degree histogram
__device__ __align__(256) int g_cur[MAX_NODES];      // fill cursor
__device__ __align__(256) int g_row[MAX_NODES + 1];  // CSR row offsets
__device__ __align__(256) int g_bsum[N_SCAN_BLOCKS]; // scan spine
__device__ __align__(256) int g_srcs[MAX_EDGES];     // CSR columns (src ids)

// ---- packed f32x2 helpers ----
__device__ __forceinline__ unsigned long long pack2(float lo, float hi) {
    unsigned long long r;
    asm("mov.b64 %0, {%1, %2};" : "=l"(r) : "f"(lo), "f"(hi));
    return r;
}
__device__ __forceinline__ void unpack2(unsigned long long v, float& lo, float& hi) {
    asm("mov.b64 {%0, %1}, %2;" : "=f"(lo), "=f"(hi) : "l"(v));
}
__device__ __forceinline__ unsigned long long ffma2(
    unsigned long long a, unsigned long long b, unsigned long long c) {
    unsigned long long d;
    asm("fma.rn.f32x2 %0, %1, %2, %3;" : "=l"(d) : "l"(a), "l"(b), "l"(c));
    return d;
}

// ---------------------------------------------------------------------------
// CSR build kernels (R3 verbatim — passed correctness)
// ---------------------------------------------------------------------------
__global__ void zero_k(int* __restrict__ c, int n) {
    int i = blockIdx.x * blockDim.x + threadIdx.x;
    if (i < n) c[i] = 0;
}

__global__ void hist_k(const int* __restrict__ ei, int* __restrict__ cnt, int e) {
    int t = blockIdx.x * blockDim.x + threadIdx.x;
    if (t < e) atomicAdd(&cnt[ei[e + t]], 1);
}

__global__ void scan_partial_k(const int* __restrict__ cnt, int* __restrict__ bsum, int n) {
    __shared__ int s[SCAN_B];
    int i = blockIdx.x * SCAN_B + threadIdx.x;
    s[threadIdx.x] = (i < n) ? cnt[i] : 0;
    __syncthreads();
    for (int off = SCAN_B / 2; off > 0; off >>= 1) {
        if (threadIdx.x < off) s[threadIdx.x] += s[threadIdx.x + off];
        __syncthreads();
    }
    if (threadIdx.x == 0) bsum[blockIdx.x] = s[0];
}

__global__ void scan_spine_k(int* __restrict__ bsum, int* __restrict__ row, int nb, int n, int e) {
    __shared__ int s[128];
    int t = threadIdx.x;
    int v = (t < nb) ? bsum[t] : 0;
    s[t] = v;
    __syncthreads();
    for (int off = 1; off < 128; off <<= 1) {
        int x = (t >= off) ? s[t - off] : 0;
        __syncthreads();
        s[t] += x;
        __syncthreads();
    }
    if (t < nb) bsum[t] = s[t] - v;  // exclusive
    if (t == 0) row[n] = e;
}

__global__ void scan_final_k(const int* __restrict__ cnt, const int* __restrict__ bsum,
                             int* __restrict__ row, int* __restrict__ cur, int n) {
    __shared__ int s[SCAN_B];
    int i = blockIdx.x * SCAN_B + threadIdx.x;
    int v = (i < n) ? cnt[i] : 0;
    s[threadIdx.x] = v;
    __syncthreads();
    for (int off = 1; off < SCAN_B; off <<= 1) {
        int x = (threadIdx.x >= off) ? s[threadIdx.x - off] : 0;
        __syncthreads();
        s[threadIdx.x] += x;
        __syncthreads();
    }
    if (i < n) {
        int excl = bsum[blockIdx.x] + s[threadIdx.x] - v;
        row[i] = excl;
        cur[i] = excl;
    }
}

__global__ void fill_k(const int* __restrict__ ei, int* __restrict__ cur,
                       int* __restrict__ srcs, int e) {
    int t = blockIdx.x * blockDim.x + threadIdx.x;
    if (t < e) {
        int dst = ei[e + t];
        int pos = atomicAdd(&cur[dst], 1);
        srcs[pos] = ei[t];
    }
}

// ---------------------------------------------------------------------------
// Dense transform (R10 verbatim — measured-good).
// ---------------------------------------------------------------------------
template <int FIN, int FOUT, bool RELU>
__global__ void transform_k(const float* __restrict__ x,
                            const float* __restrict__ Wrel,
                            const float* __restrict__ Wroot,
                            const float* __restrict__ b,
                            float* __restrict__ y,
                            float* __restrict__ h,
                            int n) {
    __shared__ __align__(16) float s_rel[FIN * FOUT];
    __shared__ __align__(16) float s_root[FIN * FOUT];
    __shared__ float s_b[FOUT];
    for (int i = threadIdx.x; i < FIN * FOUT; i += blockDim.x) {
        s_rel[i]  = Wrel[i];
        s_root[i] = Wroot[i];
    }
    for (int i = threadIdx.x; i < FOUT; i += blockDim.x) s_b[i] = b[i];
    __syncthreads();

    int node = blockIdx.x * blockDim.x + threadIdx.x;
    if (node >= n) return;

    constexpr int P = FOUT / 2;
    unsigned long long accR[P], accO[P];
#pragma unroll
    for (int p = 0; p < P; p++) { accR[p] = 0ull; accO[p] = 0ull; }

    const float4* xr = reinterpret_cast<const float4*>(x + (size_t)node * FIN);
#pragma unroll
    for (int kk = 0; kk < FIN / 4; kk++) {
        float4 xv = __ldg(xr + kk);
        float xs[4] = {xv.x, xv.y, xv.z, xv.w};
#pragma unroll
        for (int q = 0; q < 4; q++) {
            float v = RELU ? fmaxf(xs[q], 0.f) : xs[q];
            unsigned long long a = pack2(v, v);
            const int k = kk * 4 + q;
            if constexpr (FOUT >= 4) {
#pragma unroll
                for (int j4 = 0; j4 < FOUT / 4; j4++) {
                    ulonglong2 wr = *reinterpret_cast<const ulonglong2*>(&s_rel[k * FOUT + j4 * 4]);
                    ulonglong2 wo = *reinterpret_cast<const ulonglong2*>(&s_root[k * FOUT + j4 * 4]);
                    accR[j4 * 2 + 0] = ffma2(a, wr.x, accR[j4 * 2 + 0]);
                    accR[j4 * 2 + 1] = ffma2(a, wr.y, accR[j4 * 2 + 1]);
                    accO[j4 * 2 + 0] = ffma2(a, wo.x, accO[j4 * 2 + 0]);
                    accO[j4 * 2 + 1] = ffma2(a, wo.y, accO[j4 * 2 + 1]);
                }
            } else {
                unsigned long long wr = *reinterpret_cast<const unsigned long long*>(&s_rel[k * FOUT]);
                unsigned long long wo = *reinterpret_cast<const unsigned long long*>(&s_root[k * FOUT]);
                accR[0] = ffma2(a, wr, accR[0]);
                accO[0] = ffma2(a, wo, accO[0]);
            }
        }
    }

    float* yo = y + (size_t)node * FOUT;
    float* ho = h + (size_t)node * FOUT;
    float outR[FOUT], outO[FOUT];
#pragma unroll
    for (int p = 0; p < P; p++) {
        unpack2(accR[p], outR[2 * p], outR[2 * p + 1]);
        unpack2(accO[p], outO[2 * p], outO[2 * p + 1]);
    }
    if constexpr (FOUT >= 4) {
#pragma unroll
        for (int j4 = 0; j4 < FOUT / 4; j4++) {
            reinterpret_cast<float4*>(yo)[j4] =
                make_float4(outR[j4 * 4], outR[j4 * 4 + 1], outR[j4 * 4 + 2], outR[j4 * 4 + 3]);
            reinterpret_cast<float4*>(ho)[j4] =
                make_float4(outO[j4 * 4] + s_b[j4 * 4],         outO[j4 * 4 + 1] + s_b[j4 * 4 + 1],
                            outO[j4 * 4 + 2] + s_b[j4 * 4 + 2], outO[j4 * 4 + 3] + s_b[j4 * 4 + 3]);
        }
    } else {
        *reinterpret_cast<float2*>(yo) = make_float2(outR[0], outR[1]);
        *reinterpret_cast<float2*>(ho) = make_float2(outO[0] + s_b[0], outO[1] + s_b[1]);
    }
}

// ---------------------------------------------------------------------------
// Pull aggregation: thread per (node, float4-chunk). 4 independent gathers in
// flight (unroll-by-4, separate accumulators). CH consecutive threads share a
// node -> contiguous gathers of the same src row; h RMW coalesced, race-free.
// h[node] += sum_{src in N(node)} y[src]   (h already holds root + bias).
// ---------------------------------------------------------------------------
template <int F>
__global__ void agg_k(const int* __restrict__ row, const int* __restrict__ srcs,
                      const float* __restrict__ y, float* __restrict__ h, int n) {
    constexpr int CH = F / 4;
    int t = blockIdx.x * blockDim.x + threadIdx.x;
    if (t >= n * CH) return;
    int node = t / CH;
    int c = t % CH;
    int i = __ldg(row + node);
    const int end = __ldg(row + node + 1);

    float4 a0 = make_float4(0.f, 0.f, 0.f, 0.f);
    float4 a1 = a0, a2 = a0, a3 = a0;
    for (; i + 4 <= end; i += 4) {
        int s0 = __ldg(srcs + i);
        int s1 = __ldg(srcs + i + 1);
        int s2 = __ldg(srcs + i + 2);
        int s3 = __ldg(srcs + i + 3);
        float4 v0 = __ldg(reinterpret_cast<const float4*>(y + (size_t)s0 * F + c * 4));
        float4 v1 = __ldg(reinterpret_cast<const float4*>(y + (size_t)s1 * F + c * 4));
        float4 v2 = __ldg(reinterpret_cast<const float4*>(y + (size_t)s2 * F + c * 4));
        float4 v3 = __ldg(reinterpret_cast<const float4*>(y + (size_t)s3 * F + c * 4));
        a0.x += v0.x; a0.y += v0.y; a0.z += v0.z; a0.w += v0.w;
        a1.x += v1.x; a1.y += v1.y; a1.z += v1.z; a1.w += v1.w;
        a2.x += v2.x; a2.y += v2.y; a2.z += v2.z; a2.w += v2.w;
        a3.x += v3.x; a3.y += v3.y; a3.z += v3.z; a3.w += v3.w;
    }
    for (; i < end; i++) {
        int s = __ldg(srcs + i);
        float4 v = __ldg(reinterpret_cast<const float4*>(y + (size_t)s * F + c * 4));
        a0.x += v.x; a0.y += v.y; a0.z += v.z; a0.w += v.w;
    }
    float4 acc = make_float4(a0.x + a1.x + a2.x + a3.x,
                             a0.y + a1.y + a2.y + a3.y,
                             a0.z + a1.z + a2.z + a3.z,
                             a0.w + a1.w + a2.w + a3.w);
    float4* hp = reinterpret_cast<float4*>(h + (size_t)node * F) + c;
    float4 r = *hp;
    r.x += acc.x; r.y += acc.y; r.z += acc.z; r.w += acc.w;
    *hp = r;
}

// Layer-3 pull aggregation (F=2) fused with 2-class softmax. One thread/node.
__global__ void agg3_softmax_k(const int* __restrict__ row, const int* __restrict__ srcs,
                               const float* __restrict__ y, const float* __restrict__ h,
                               float* __restrict__ out, int n) {
    int node = blockIdx.x * blockDim.x + threadIdx.x;
    if (node >= n) return;
    int i = __ldg(row + node);
    const int end = __ldg(row + node + 1);

    float ax0 = 0.f, ay0 = 0.f, ax1 = 0.f, ay1 = 0.f;
    float ax2 = 0.f, ay2 = 0.f, ax3 = 0.f, ay3 = 0.f;
    for (; i + 4 <= end; i += 4) {
        int s0 = __ldg(srcs + i);
        int s1 = __ldg(srcs + i + 1);
        int s2 = __ldg(srcs + i + 2);
        int s3 = __ldg(srcs + i + 3);
        float2 v0 = __ldg(reinterpret_cast<const float2*>(y + 2 * (size_t)s0));
        float2 v1 = __ldg(reinterpret_cast<const float2*>(y + 2 * (size_t)s1));
        float2 v2 = __ldg(reinterpret_cast<const float2*>(y + 2 * (size_t)s2));
        float2 v3 = __ldg(reinterpret_cast<const float2*>(y + 2 * (size_t)s3));
        ax0 += v0.x; ay0 += v0.y;
        ax1 += v1.x; ay1 += v1.y;
        ax2 += v2.x; ay2 += v2.y;
        ax3 += v3.x; ay3 += v3.y;
    }
    for (; i < end; i++) {
        int s = __ldg(srcs + i);
        float2 v = __ldg(reinterpret_cast<const float2*>(y + 2 * (size_t)s));
        ax0 += v.x; ay0 += v.y;
    }
    float ax = (ax0 + ax1) + (ax2 + ax3);
    float ay = (ay0 + ay1) + (ay2 + ay3);

    float2 r = *reinterpret_cast<const float2*>(h + 2 * (size_t)node);
    float vx = r.x + ax, vy = r.y + ay;
    float m  = fmaxf(vx, vy);
    float ea = __expf(vx - m);
    float eb = __expf(vy - m);
    float inv = 1.0f / (ea + eb);
    reinterpret_cast<float2*>(out)[node] = make_float2(ea * inv, eb * inv);
}

extern "C" void kernel_launch(void* const* d_in, const int* in_sizes, int n_in,
                              void* d_out, int out_size) {
    const float* z      = (const float*)d_in[0];
    const int*   ei     = (const int*)d_in[1];   // int32 (JAX x64 disabled)
    const float* Wrel1  = (const float*)d_in[2];
    const float* Wroot1 = (const float*)d_in[3];
    const float* b1     = (const float*)d_in[4];
    const float* Wrel2  = (const float*)d_in[5];
    const float* Wroot2 = (const float*)d_in[6];
    const float* b2     = (const float*)d_in[7];
    const float* Wrel3  = (const float*)d_in[8];
    const float* Wroot3 = (const float*)d_in[9];
    const float* b3     = (const float*)d_in[10];

    const int n = in_sizes[0] / 64;   // 100000
    const int e = in_sizes[1] / 2;    // 1600000

    float *y1, *h1, *y2, *h2, *y3, *h3;
    int *cnt, *cur, *rowp, *bsum, *srcs;
    cudaGetSymbolAddress((void**)&y1, g_y1);
    cudaGetSymbolAddress((void**)&h1, g_h1);
    cudaGetSymbolAddress((void**)&y2, g_y2);
    cudaGetSymbolAddress((void**)&h2, g_h2);
    cudaGetSymbolAddress((void**)&y3, g_y3);
    cudaGetSymbolAddress((void**)&h3, g_h3);
    cudaGetSymbolAddress((void**)&cnt,  g_cnt);
    cudaGetSymbolAddress((void**)&cur,  g_cur);
    cudaGetSymbolAddress((void**)&rowp, g_row);
    cudaGetSymbolAddress((void**)&bsum, g_bsum);
    cudaGetSymbolAddress((void**)&srcs, g_srcs);

    const int nScanBlocks = (n + SCAN_B - 1) / SCAN_B;  // 98
    const int TB = 128;
    const int nodeBlocks = (n + TB - 1) / TB;
    const int edgeBlocks = (e + 255) / 256;

    // ---- CSR build (also overlaps with nothing; layer-1 transform is
    // independent of it, so interleave the launches for pipeline slack) ----
    zero_k<<<(n + 255) / 256, 256>>>(cnt, n);
    transform_k<64, F1, false><<<nodeBlocks, TB>>>(z, Wrel1, Wroot1, b1, y1, h1, n);
    hist_k<<<edgeBlocks, 256>>>(ei, cnt, e);
    scan_partial_k<<<nScanBlocks, SCAN_B>>>(cnt, bsum, n);
    scan_spine_k<<<1, 128>>>(bsum, rowp, nScanBlocks, n, e);
    scan_final_k<<<nScanBlocks, SCAN_B>>>(cnt, bsum, rowp, cur, n);
    fill_k<<<edgeBlocks, 256>>>(ei, cur, srcs, e);

    // ---- Layer 1 aggregation (pull; no atomics) ----
    {
        int total = n * (F1 / 4);
        agg_k<F1><<<(total + 255) / 256, 256>>>(rowp, srcs, y1, h1, n);
    }
    // ---- Layer 2 ----
    transform_k<F1, F2, true><<<nodeBlocks, TB>>>(h1, Wrel2, Wroot2, b2, y2, h2, n);
    {
        int total = n * (F2 / 4);
        agg_k<F2><<<(total + 255) / 256, 256>>>(rowp, srcs, y2, h2, n);
    }
    // ---- Layer 3 + fused softmax ----
    transform_k<F2, F3, true><<<nodeBlocks, TB>>>(h2, Wrel3, Wroot3, b3, y3, h3, n);
    agg3_softmax_k<<<(n + 255) / 256, 256>>>(rowp, srcs, y3, h3, (float*)d_out, n);
}